// round 6
// baseline (speedup 1.0000x reference)
#include <cuda_runtime.h>
#include <cuda_fp16.h>
#include <cstdint>
#include <math.h>

// ---------------------------------------------------------------------------
// Problem constants
// ---------------------------------------------------------------------------
#define B_     4096
#define NIN    2048
#define NOUT   2048
#define KTOT   4096              // NIN + NOUT
#define NTOT   8192              // 4 * NOUT

// GEMM tiling: 256(M) x 128(N-packed) x 64(K), 256 threads, 8 warps (4m x 2n),
// warp tile 64x64.
#define BM     256
#define BN     128
#define BK     64
#define STG    3
#define A_STAGE_B  (BM * BK * 2)             // 32768
#define B_STAGE_B  (BN * BK * 2)             // 16384
#define STAGE_B    (A_STAGE_B + B_STAGE_B)   // 49152
#define SMEM_TOTAL (STG * STAGE_B)           // 147456
#define EPI_PITCH  136                        // fp32 words per row (128 + 8 pad)

// ---------------------------------------------------------------------------
// Device scratch (static; no allocation allowed)
// ---------------------------------------------------------------------------
__device__ __align__(16) __half g_Th[(size_t)B_ * KTOT];     // 32 MB
__device__ __align__(16) __half g_Wh[(size_t)NTOT * KTOT];   // 64 MB (rows: j*4+gate)

// ---------------------------------------------------------------------------
// Helpers
// ---------------------------------------------------------------------------
__device__ __forceinline__ uint32_t smem_u32(const void* p) {
    uint32_t a;
    asm("{ .reg .u64 t; cvta.to.shared.u64 t, %1; cvt.u32.u64 %0, t; }" : "=r"(a) : "l"(p));
    return a;
}

__device__ __forceinline__ uint32_t swz(uint32_t off) {
    return off ^ ((off >> 3) & 0x70);     // 128B-row swizzle
}

__device__ __forceinline__ void cp16(uint32_t dst, const void* src) {
    asm volatile("cp.async.cg.shared.global [%0], [%1], 16;" :: "r"(dst), "l"(src));
}

__device__ __forceinline__ void ldsm4(uint32_t* d, uint32_t addr) {
    asm volatile("ldmatrix.sync.aligned.m8n8.x4.shared.b16 {%0,%1,%2,%3}, [%4];"
                 : "=r"(d[0]), "=r"(d[1]), "=r"(d[2]), "=r"(d[3]) : "r"(addr));
}

__device__ __forceinline__ void mma16816(float* c,
                                         uint32_t a0, uint32_t a1, uint32_t a2, uint32_t a3,
                                         uint32_t b0, uint32_t b1) {
    asm volatile("mma.sync.aligned.m16n8k16.row.col.f32.f16.f16.f32 "
                 "{%0,%1,%2,%3}, {%4,%5,%6,%7}, {%8,%9}, {%0,%1,%2,%3};"
                 : "+f"(c[0]), "+f"(c[1]), "+f"(c[2]), "+f"(c[3])
                 : "r"(a0), "r"(a1), "r"(a2), "r"(a3), "r"(b0), "r"(b1));
}

__device__ __forceinline__ float sigmoidf_(float z) { return 1.0f / (1.0f + expf(-z)); }

// ---------------------------------------------------------------------------
// Conversion kernels: fp32 -> fp16
// ---------------------------------------------------------------------------
__device__ __forceinline__ uint4 pack8_h(const float* src) {
    float4 v0 = *reinterpret_cast<const float4*>(src);
    float4 v1 = *reinterpret_cast<const float4*>(src + 4);
    __half2 p0 = __floats2half2_rn(v0.x, v0.y);
    __half2 p1 = __floats2half2_rn(v0.z, v0.w);
    __half2 p2 = __floats2half2_rn(v1.x, v1.y);
    __half2 p3 = __floats2half2_rn(v1.z, v1.w);
    uint4 o;
    o.x = *reinterpret_cast<uint32_t*>(&p0);
    o.y = *reinterpret_cast<uint32_t*>(&p1);
    o.z = *reinterpret_cast<uint32_t*>(&p2);
    o.w = *reinterpret_cast<uint32_t*>(&p3);
    return o;
}

__global__ void __launch_bounds__(256)
conv_T_kernel(const float* __restrict__ x, const float* __restrict__ h) {
    uint32_t idx = blockIdx.x * 256 + threadIdx.x;   // B_ * 512 threads
    uint32_t m = idx >> 9;
    uint32_t k = (idx & 511) * 8;
    const float* src = (k < NIN) ? (x + (size_t)m * NIN + k)
                                 : (h + (size_t)m * NOUT + (k - NIN));
    *reinterpret_cast<uint4*>(g_Th + (size_t)m * KTOT + k) = pack8_h(src);
}

// Packed W rows: p = j*4 + gate, so a 128-row band = 32 j's x 4 gates.
__global__ void __launch_bounds__(256)
conv_W_kernel(const float* __restrict__ Wf, const float* __restrict__ Wi,
              const float* __restrict__ Wo, const float* __restrict__ Wg) {
    uint32_t idx = blockIdx.x * 256 + threadIdx.x;   // NTOT * 512 threads
    uint32_t jall = idx >> 9;                         // 0..8191 (gate*2048 + j)
    uint32_t k = (idx & 511) * 8;
    uint32_t gate = jall >> 11;
    uint32_t j = jall & 2047;
    const float* W = (gate == 0) ? Wf : (gate == 1) ? Wi : (gate == 2) ? Wo : Wg;
    uint32_t p = j * 4 + gate;
    *reinterpret_cast<uint4*>(g_Wh + (size_t)p * KTOT + k) =
        pack8_h(W + (size_t)j * KTOT + k);
}

// ---------------------------------------------------------------------------
// Fused GEMM + LSTM epilogue.
// grid = 1024 (mt = bid&15, nt = bid>>4), 256 threads, 3-stage cp.async.
// ---------------------------------------------------------------------------
__device__ __forceinline__ void stage_slab(uint32_t sA, uint32_t sB,
                                           const __half* __restrict__ gA,
                                           const __half* __restrict__ gB,
                                           int k0, int t) {
    // A: 256 rows x 8 chunks of 16B = 2048 chunks -> 8 per thread
#pragma unroll
    for (int i = 0; i < 8; i++) {
        int c = t + i * 256;
        int row = c >> 3, c16 = c & 7;
        uint32_t off = row * 128 + c16 * 16;
        cp16(sA + swz(off), gA + (size_t)row * KTOT + k0 + c16 * 8);
    }
    // B: 128 rows x 8 chunks = 1024 chunks -> 4 per thread
#pragma unroll
    for (int i = 0; i < 4; i++) {
        int c = t + i * 256;
        int row = c >> 3, c16 = c & 7;
        uint32_t off = row * 128 + c16 * 16;
        cp16(sB + swz(off), gB + (size_t)row * KTOT + k0 + c16 * 8);
    }
}

__global__ void __launch_bounds__(256, 1)
lstm_gemm_fused_kernel(const float* __restrict__ c_old,
                       const float* __restrict__ bf,
                       const float* __restrict__ bi,
                       const float* __restrict__ bo,
                       const float* __restrict__ bg,
                       float* __restrict__ out) {
    extern __shared__ __align__(1024) char smem[];
    const uint32_t sbase = smem_u32(smem);

    const int t    = threadIdx.x;
    const int lane = t & 31;
    const int wid  = t >> 5;      // 0..7
    const int wm   = wid & 3;     // warp m band: 64 rows
    const int wn   = wid >> 2;    // warp n band: 64 packed cols

    const int bid = blockIdx.x;
    const int mt = bid & 15;
    const int nt = bid >> 4;
    const int m0 = mt * BM;
    const int p0 = nt * BN;       // packed col base
    const int j0 = nt * 32;       // j base

    const __half* gA = g_Th + (size_t)m0 * KTOT;
    const __half* gB = g_Wh + (size_t)p0 * KTOT;

    float acc[4][8][4];           // [mf][n8][quad]
#pragma unroll
    for (int i = 0; i < 4; i++)
#pragma unroll
        for (int j = 0; j < 8; j++)
#pragma unroll
            for (int q = 0; q < 4; q++) acc[i][j][q] = 0.0f;

    stage_slab(sbase, sbase + A_STAGE_B, gA, gB, 0, t);
    asm volatile("cp.async.commit_group;" ::: "memory");
    stage_slab(sbase + STAGE_B, sbase + STAGE_B + A_STAGE_B, gA, gB, BK, t);
    asm volatile("cp.async.commit_group;" ::: "memory");

    const int lrow = lane & 15;
    const int lkof = (lane & 16) ? 8 : 0;

    const int NIT = KTOT / BK;     // 64
    for (int it = 0; it < NIT; it++) {
        asm volatile("cp.async.wait_group 1;" ::: "memory");
        __syncthreads();

        if (it + 2 < NIT) {
            int sn = (it + 2) % STG;
            stage_slab(sbase + sn * STAGE_B, sbase + sn * STAGE_B + A_STAGE_B,
                       gA, gB, (it + 2) * BK, t);
            asm volatile("cp.async.commit_group;" ::: "memory");
        }

        const int s = it % STG;
        const uint32_t aA = sbase + s * STAGE_B;
        const uint32_t aB = aA + A_STAGE_B;

#pragma unroll
        for (int kk = 0; kk < 4; kk++) {
            uint32_t a[4][4], b[4][4];
#pragma unroll
            for (int mf = 0; mf < 4; mf++) {
                uint32_t off = (uint32_t)(wm * 64 + mf * 16 + lrow) * 128
                             + (uint32_t)(kk * 16 + lkof) * 2;
                ldsm4(a[mf], aA + swz(off));
            }
#pragma unroll
            for (int nf = 0; nf < 4; nf++) {
                uint32_t off = (uint32_t)(wn * 64 + nf * 16 + lrow) * 128
                             + (uint32_t)(kk * 16 + lkof) * 2;
                ldsm4(b[nf], aB + swz(off));
            }
#pragma unroll
            for (int nf = 0; nf < 4; nf++) {
#pragma unroll
                for (int mf = 0; mf < 4; mf++) {
                    mma16816(acc[mf][nf * 2],     a[mf][0], a[mf][1], a[mf][2], a[mf][3],
                             b[nf][0], b[nf][2]);
                    mma16816(acc[mf][nf * 2 + 1], a[mf][0], a[mf][1], a[mf][2], a[mf][3],
                             b[nf][1], b[nf][3]);
                }
            }
        }
    }

    // ---- drain pipeline, then reuse smem as fp32 Z tile [256][EPI_PITCH] ----
    asm volatile("cp.async.wait_group 0;" ::: "memory");
    __syncthreads();

    float* zt = reinterpret_cast<float*>(smem);
    {
        const int r0 = wm * 64 + (lane >> 2);
        const int c0 = wn * 64 + (lane & 3) * 2;
#pragma unroll
        for (int mf = 0; mf < 4; mf++) {
            int row = r0 + mf * 16;
#pragma unroll
            for (int n8 = 0; n8 < 8; n8++) {
                int pc = c0 + n8 * 8;
                *reinterpret_cast<float2*>(&zt[(size_t)row * EPI_PITCH + pc]) =
                    make_float2(acc[mf][n8][0], acc[mf][n8][1]);
                *reinterpret_cast<float2*>(&zt[(size_t)(row + 8) * EPI_PITCH + pc]) =
                    make_float2(acc[mf][n8][2], acc[mf][n8][3]);
            }
        }
    }
    __syncthreads();

    // ---- fused LSTM epilogue: warp -> 32-row block, lane -> j ----
    {
        const int j = lane;                  // 0..31
        const int jg = j0 + j;
        const float bfs = bf[jg];
        const float bis = bi[jg];
        const float bos = bo[jg];
        const float bgs = bg[jg];
        const int wb = wid;                  // 0..7, each covers 32 rows
#pragma unroll
        for (int i = 0; i < 32; i++) {
            int ml = wb * 32 + i;
            float4 z = *reinterpret_cast<const float4*>(&zt[(size_t)ml * EPI_PITCH + j * 4]);
            float zf = z.x + bfs;
            float zi = z.y + bis;
            float zo = z.z + bos;
            float zg = z.w + bgs;
            int m = m0 + ml;
            float co = c_old[(size_t)m * NOUT + jg];
            float f  = sigmoidf_(zf);
            float ii = sigmoidf_(zi);
            float oo = sigmoidf_(zo);
            float g  = tanhf(zg);
            float c  = f * co + ii * g;
            float hh = oo * tanhf(c);
            out[(size_t)m * NOUT + jg] = c;
            out[(size_t)B_ * NOUT + (size_t)m * NOUT + jg] = hh;
        }
    }
}

// ---------------------------------------------------------------------------
// kernel_launch
// Input order: c_old, h_old, x, Wf, bf, Wi, bi, Wo, bo, Wg, bg, mode
// ---------------------------------------------------------------------------
extern "C" void kernel_launch(void* const* d_in, const int* in_sizes, int n_in,
                              void* d_out, int out_size) {
    const float* c_old = (const float*)d_in[0];
    const float* h_old = (const float*)d_in[1];
    const float* x     = (const float*)d_in[2];
    const float* Wf    = (const float*)d_in[3];
    const float* bf    = (const float*)d_in[4];
    const float* Wi    = (const float*)d_in[5];
    const float* bi    = (const float*)d_in[6];
    const float* Wo    = (const float*)d_in[7];
    const float* bo    = (const float*)d_in[8];
    const float* Wg    = (const float*)d_in[9];
    const float* bg    = (const float*)d_in[10];
    float* out = (float*)d_out;

    static int configured = 0;
    if (!configured) {
        cudaFuncSetAttribute(lstm_gemm_fused_kernel,
                             cudaFuncAttributeMaxDynamicSharedMemorySize, SMEM_TOTAL);
        configured = 1;
    }

    conv_T_kernel<<<(B_ * 512) / 256, 256>>>(x, h_old);
    conv_W_kernel<<<(NTOT * 512) / 256, 256>>>(Wf, Wi, Wo, Wg);

    lstm_gemm_fused_kernel<<<(B_ / BM) * (NTOT / BN), 256, SMEM_TOTAL>>>(
        c_old, bf, bi, bo, bg, out);
}

// round 7
// speedup vs baseline: 1.1175x; 1.1175x over previous
#include <cuda_runtime.h>
#include <cuda_fp16.h>
#include <cstdint>
#include <math.h>

// ---------------------------------------------------------------------------
// Problem constants
// ---------------------------------------------------------------------------
#define B_     4096
#define NIN    2048
#define NOUT   2048
#define KTOT   4096              // NIN + NOUT
#define NTOT   8192              // 4 * NOUT

// GEMM tiling: 128(M) x 128(N-packed) x 64(K), 256 threads, 8 warps (4m x 2n),
// warp tile 32x64, 2 CTAs/SM.
#define BM     128
#define BN     128
#define BK     64
#define STG    3
#define A_STAGE_B  (BM * BK * 2)             // 16384
#define B_STAGE_B  (BN * BK * 2)             // 16384
#define STAGE_B    (A_STAGE_B + B_STAGE_B)   // 32768
#define SMEM_TOTAL (STG * STAGE_B)           // 98304 -> 2 CTAs/SM
#define EPI_PITCH  132                        // fp32 words per row (128 + 4 pad)

// ---------------------------------------------------------------------------
// Device scratch (static; no allocation allowed)
// ---------------------------------------------------------------------------
__device__ __align__(16) __half g_Th[(size_t)B_ * KTOT];     // 32 MB
__device__ __align__(16) __half g_Wh[(size_t)NTOT * KTOT];   // 64 MB (rows: j*4+gate)

// ---------------------------------------------------------------------------
// Helpers
// ---------------------------------------------------------------------------
__device__ __forceinline__ uint32_t smem_u32(const void* p) {
    uint32_t a;
    asm("{ .reg .u64 t; cvta.to.shared.u64 t, %1; cvt.u32.u64 %0, t; }" : "=r"(a) : "l"(p));
    return a;
}

__device__ __forceinline__ uint32_t swz(uint32_t off) {
    return off ^ ((off >> 3) & 0x70);     // 128B-row swizzle
}

__device__ __forceinline__ void cp16(uint32_t dst, const void* src) {
    asm volatile("cp.async.cg.shared.global [%0], [%1], 16;" :: "r"(dst), "l"(src));
}

__device__ __forceinline__ void ldsm4(uint32_t* d, uint32_t addr) {
    asm volatile("ldmatrix.sync.aligned.m8n8.x4.shared.b16 {%0,%1,%2,%3}, [%4];"
                 : "=r"(d[0]), "=r"(d[1]), "=r"(d[2]), "=r"(d[3]) : "r"(addr));
}

__device__ __forceinline__ void mma16816(float* c,
                                         uint32_t a0, uint32_t a1, uint32_t a2, uint32_t a3,
                                         uint32_t b0, uint32_t b1) {
    asm volatile("mma.sync.aligned.m16n8k16.row.col.f32.f16.f16.f32 "
                 "{%0,%1,%2,%3}, {%4,%5,%6,%7}, {%8,%9}, {%0,%1,%2,%3};"
                 : "+f"(c[0]), "+f"(c[1]), "+f"(c[2]), "+f"(c[3])
                 : "r"(a0), "r"(a1), "r"(a2), "r"(a3), "r"(b0), "r"(b1));
}

__device__ __forceinline__ float sigmoidf_(float z) { return 1.0f / (1.0f + expf(-z)); }

// ---------------------------------------------------------------------------
// Conversion kernels: fp32 -> fp16
// ---------------------------------------------------------------------------
__device__ __forceinline__ uint4 pack8_h(const float* src) {
    float4 v0 = *reinterpret_cast<const float4*>(src);
    float4 v1 = *reinterpret_cast<const float4*>(src + 4);
    __half2 p0 = __floats2half2_rn(v0.x, v0.y);
    __half2 p1 = __floats2half2_rn(v0.z, v0.w);
    __half2 p2 = __floats2half2_rn(v1.x, v1.y);
    __half2 p3 = __floats2half2_rn(v1.z, v1.w);
    uint4 o;
    o.x = *reinterpret_cast<uint32_t*>(&p0);
    o.y = *reinterpret_cast<uint32_t*>(&p1);
    o.z = *reinterpret_cast<uint32_t*>(&p2);
    o.w = *reinterpret_cast<uint32_t*>(&p3);
    return o;
}

__global__ void __launch_bounds__(256)
conv_T_kernel(const float* __restrict__ x, const float* __restrict__ h) {
    uint32_t idx = blockIdx.x * 256 + threadIdx.x;   // B_ * 512 threads
    uint32_t m = idx >> 9;
    uint32_t k = (idx & 511) * 8;
    const float* src = (k < NIN) ? (x + (size_t)m * NIN + k)
                                 : (h + (size_t)m * NOUT + (k - NIN));
    *reinterpret_cast<uint4*>(g_Th + (size_t)m * KTOT + k) = pack8_h(src);
}

// Packed W rows: p = j*4 + gate, so a 128-row band = 32 j's x 4 gates.
__global__ void __launch_bounds__(256)
conv_W_kernel(const float* __restrict__ Wf, const float* __restrict__ Wi,
              const float* __restrict__ Wo, const float* __restrict__ Wg) {
    uint32_t idx = blockIdx.x * 256 + threadIdx.x;   // NTOT * 512 threads
    uint32_t jall = idx >> 9;                         // 0..8191 (gate*2048 + j)
    uint32_t k = (idx & 511) * 8;
    uint32_t gate = jall >> 11;
    uint32_t j = jall & 2047;
    const float* W = (gate == 0) ? Wf : (gate == 1) ? Wi : (gate == 2) ? Wo : Wg;
    uint32_t p = j * 4 + gate;
    *reinterpret_cast<uint4*>(g_Wh + (size_t)p * KTOT + k) =
        pack8_h(W + (size_t)j * KTOT + k);
}

// ---------------------------------------------------------------------------
// Fused GEMM + LSTM epilogue.
// grid = 2048 (mt = bid&31, nt = bid>>5), 256 threads, 3-stage cp.async.
// ---------------------------------------------------------------------------
__device__ __forceinline__ void stage_slab(uint32_t sA, uint32_t sB,
                                           const __half* __restrict__ gA,
                                           const __half* __restrict__ gB,
                                           int k0, int t) {
    // A: 128 rows x 8 chunks of 16B = 1024 chunks -> 4 per thread
#pragma unroll
    for (int i = 0; i < 4; i++) {
        int c = t + i * 256;
        int row = c >> 3, c16 = c & 7;
        uint32_t off = row * 128 + c16 * 16;
        cp16(sA + swz(off), gA + (size_t)row * KTOT + k0 + c16 * 8);
    }
    // B: 128 rows x 8 chunks = 1024 chunks -> 4 per thread
#pragma unroll
    for (int i = 0; i < 4; i++) {
        int c = t + i * 256;
        int row = c >> 3, c16 = c & 7;
        uint32_t off = row * 128 + c16 * 16;
        cp16(sB + swz(off), gB + (size_t)row * KTOT + k0 + c16 * 8);
    }
}

__global__ void __launch_bounds__(256, 2)
lstm_gemm_fused_kernel(const float* __restrict__ c_old,
                       const float* __restrict__ bf,
                       const float* __restrict__ bi,
                       const float* __restrict__ bo,
                       const float* __restrict__ bg,
                       float* __restrict__ out) {
    extern __shared__ __align__(1024) char smem[];
    const uint32_t sbase = smem_u32(smem);

    const int t    = threadIdx.x;
    const int lane = t & 31;
    const int wid  = t >> 5;      // 0..7
    const int wm   = wid & 3;     // warp m band: 32 rows
    const int wn   = wid >> 2;    // warp n band: 64 packed cols

    const int bid = blockIdx.x;
    const int mt = bid & 31;
    const int nt = bid >> 5;
    const int m0 = mt * BM;
    const int p0 = nt * BN;       // packed col base
    const int j0 = nt * 32;       // j base

    const __half* gA = g_Th + (size_t)m0 * KTOT;
    const __half* gB = g_Wh + (size_t)p0 * KTOT;

    float acc[2][8][4];           // [mf][n8][quad]
#pragma unroll
    for (int i = 0; i < 2; i++)
#pragma unroll
        for (int j = 0; j < 8; j++)
#pragma unroll
            for (int q = 0; q < 4; q++) acc[i][j][q] = 0.0f;

    stage_slab(sbase, sbase + A_STAGE_B, gA, gB, 0, t);
    asm volatile("cp.async.commit_group;" ::: "memory");
    stage_slab(sbase + STAGE_B, sbase + STAGE_B + A_STAGE_B, gA, gB, BK, t);
    asm volatile("cp.async.commit_group;" ::: "memory");

    const int lrow = lane & 15;
    const int lkof = (lane & 16) ? 8 : 0;

    const int NIT = KTOT / BK;     // 64
    for (int it = 0; it < NIT; it++) {
        asm volatile("cp.async.wait_group 1;" ::: "memory");
        __syncthreads();

        if (it + 2 < NIT) {
            int sn = (it + 2) % STG;
            stage_slab(sbase + sn * STAGE_B, sbase + sn * STAGE_B + A_STAGE_B,
                       gA, gB, (it + 2) * BK, t);
            asm volatile("cp.async.commit_group;" ::: "memory");
        }

        const int s = it % STG;
        const uint32_t aA = sbase + s * STAGE_B;
        const uint32_t aB = aA + A_STAGE_B;

#pragma unroll
        for (int kk = 0; kk < 4; kk++) {
            uint32_t a[2][4], b[4][4];
#pragma unroll
            for (int mf = 0; mf < 2; mf++) {
                uint32_t off = (uint32_t)(wm * 32 + mf * 16 + lrow) * 128
                             + (uint32_t)(kk * 16 + lkof) * 2;
                ldsm4(a[mf], aA + swz(off));
            }
#pragma unroll
            for (int nf = 0; nf < 4; nf++) {
                uint32_t off = (uint32_t)(wn * 64 + nf * 16 + lrow) * 128
                             + (uint32_t)(kk * 16 + lkof) * 2;
                ldsm4(b[nf], aB + swz(off));
            }
#pragma unroll
            for (int nf = 0; nf < 4; nf++) {
#pragma unroll
                for (int mf = 0; mf < 2; mf++) {
                    mma16816(acc[mf][nf * 2],     a[mf][0], a[mf][1], a[mf][2], a[mf][3],
                             b[nf][0], b[nf][2]);
                    mma16816(acc[mf][nf * 2 + 1], a[mf][0], a[mf][1], a[mf][2], a[mf][3],
                             b[nf][1], b[nf][3]);
                }
            }
        }
    }

    // ---- drain pipeline, then reuse smem as fp32 Z tile [128][EPI_PITCH] ----
    asm volatile("cp.async.wait_group 0;" ::: "memory");
    __syncthreads();

    float* zt = reinterpret_cast<float*>(smem);
    {
        const int r0 = wm * 32 + (lane >> 2);
        const int c0 = wn * 64 + (lane & 3) * 2;
#pragma unroll
        for (int mf = 0; mf < 2; mf++) {
            int row = r0 + mf * 16;
#pragma unroll
            for (int n8 = 0; n8 < 8; n8++) {
                int pc = c0 + n8 * 8;
                *reinterpret_cast<float2*>(&zt[(size_t)row * EPI_PITCH + pc]) =
                    make_float2(acc[mf][n8][0], acc[mf][n8][1]);
                *reinterpret_cast<float2*>(&zt[(size_t)(row + 8) * EPI_PITCH + pc]) =
                    make_float2(acc[mf][n8][2], acc[mf][n8][3]);
            }
        }
    }
    __syncthreads();

    // ---- fused LSTM epilogue: warp -> 16-row block, lane -> j ----
    {
        const int j = lane;                  // 0..31
        const int jg = j0 + j;
        const float bfs = bf[jg];
        const float bis = bi[jg];
        const float bos = bo[jg];
        const float bgs = bg[jg];
#pragma unroll
        for (int i = 0; i < 16; i++) {
            int ml = wid * 16 + i;
            float4 z = *reinterpret_cast<const float4*>(&zt[(size_t)ml * EPI_PITCH + j * 4]);
            float zf = z.x + bfs;
            float zi = z.y + bis;
            float zo = z.z + bos;
            float zg = z.w + bgs;
            int m = m0 + ml;
            float co = c_old[(size_t)m * NOUT + jg];
            float f  = sigmoidf_(zf);
            float ii = sigmoidf_(zi);
            float oo = sigmoidf_(zo);
            float g  = tanhf(zg);
            float c  = f * co + ii * g;
            float hh = oo * tanhf(c);
            out[(size_t)m * NOUT + jg] = c;
            out[(size_t)B_ * NOUT + (size_t)m * NOUT + jg] = hh;
        }
    }
}

// ---------------------------------------------------------------------------
// kernel_launch
// Input order: c_old, h_old, x, Wf, bf, Wi, bi, Wo, bo, Wg, bg, mode
// ---------------------------------------------------------------------------
extern "C" void kernel_launch(void* const* d_in, const int* in_sizes, int n_in,
                              void* d_out, int out_size) {
    const float* c_old = (const float*)d_in[0];
    const float* h_old = (const float*)d_in[1];
    const float* x     = (const float*)d_in[2];
    const float* Wf    = (const float*)d_in[3];
    const float* bf    = (const float*)d_in[4];
    const float* Wi    = (const float*)d_in[5];
    const float* bi    = (const float*)d_in[6];
    const float* Wo    = (const float*)d_in[7];
    const float* bo    = (const float*)d_in[8];
    const float* Wg    = (const float*)d_in[9];
    const float* bg    = (const float*)d_in[10];
    float* out = (float*)d_out;

    static int configured = 0;
    if (!configured) {
        cudaFuncSetAttribute(lstm_gemm_fused_kernel,
                             cudaFuncAttributeMaxDynamicSharedMemorySize, SMEM_TOTAL);
        configured = 1;
    }

    conv_T_kernel<<<(B_ * 512) / 256, 256>>>(x, h_old);
    conv_W_kernel<<<(NTOT * 512) / 256, 256>>>(Wf, Wi, Wo, Wg);

    lstm_gemm_fused_kernel<<<(B_ / BM) * (NTOT / BN), 256, SMEM_TOTAL>>>(
        c_old, bf, bi, bo, bg, out);
}